// round 1
// baseline (speedup 1.0000x reference)
#include <cuda_runtime.h>
#include <cstdint>

// ---------------- scratch (no allocations allowed) ----------------
#define B_ 16
#define C_ 21
#define D_ 512
#define HW_ 4096          // 64*64
#define LW_ 513

__device__ unsigned char g_lab[B_ * HW_];          // resized labels as u8
__device__ int           g_cnt[B_ * C_];           // per-image class counts
__device__ float         g_sums[B_ * C_ * D_];     // pooled sums
__device__ float         g_prot[B_ * C_ * D_];     // normalized protos
__device__ float         g_pAll[C_ * C_];          // sum exp(S-10) per (c,e) block
__device__ float         g_pPos[C_];               // sum of valid diag S values
__device__ int           g_pCnt[C_];               // count of valid diag entries

// ---------------- K1: bilinear resize (half-pixel, exact) + histogram ----------------
__global__ void k1_resize_hist(const int* __restrict__ labels) {
    int b = blockIdx.x;
    __shared__ int hist[C_];
    if (threadIdx.x < C_) hist[threadIdx.x] = 0;
    __syncthreads();

    const int* L = labels + (size_t)b * LW_ * LW_;
    for (int p = threadIdx.x; p < HW_; p += blockDim.x) {
        int y = p >> 6, x = p & 63;
        // src = (i+0.5)*513/64 - 0.5 ; all exact in fp32 (multiples of 1/128)
        float sy = (y + 0.5f) * 8.015625f - 0.5f;
        float sx = (x + 0.5f) * 8.015625f - 0.5f;
        int y0 = (int)sy; float wy = sy - (float)y0;
        int x0 = (int)sx; float wx = sx - (float)x0;
        const int* r0 = L + y0 * LW_ + x0;
        const int* r1 = r0 + LW_;
        float v00 = (float)r0[0], v01 = (float)r0[1];
        float v10 = (float)r1[0], v11 = (float)r1[1];
        float v = (1.0f - wy) * ((1.0f - wx) * v00 + wx * v01)
                +          wy * ((1.0f - wx) * v10 + wx * v11);
        int c = (int)v;   // truncation, matches .astype(int32); v exact
        g_lab[b * HW_ + p] = (unsigned char)c;
        atomicAdd(&hist[c], 1);
    }
    __syncthreads();
    if (threadIdx.x < C_) g_cnt[b * C_ + threadIdx.x] = hist[threadIdx.x];
}

// ---------------- K2: masked per-class pooling (the 134 MB pass) ----------------
// grid: (16, 64) ; block handles image b, channels [dt*8, dt*8+8)
#define DT_ 8
__global__ __launch_bounds__(256) void k2_pool(const float* __restrict__ feat) {
    int b  = blockIdx.x;
    int dt = blockIdx.y;
    int tid = threadIdx.x;

    __shared__ unsigned char slab[HW_];
    __shared__ float bins[C_ * 256];   // bins[c*256 + tid] : per-thread private, conflict-free

    // labels -> smem (4096 B)
    ((uint4*)slab)[tid] = ((const uint4*)(g_lab + b * HW_))[tid];
    __syncthreads();

    for (int dd = 0; dd < DT_; dd++) {
        int d = dt * DT_ + dd;
        #pragma unroll
        for (int c = 0; c < C_; c++) bins[c * 256 + tid] = 0.0f;
        // no barrier needed: each thread touches only its own column until reduce

        const float4* F = (const float4*)(feat + ((size_t)(b * D_ + d)) * HW_);
        #pragma unroll
        for (int k = 0; k < 4; k++) {
            int p4 = k * 256 + tid;
            float4 f = __ldcs(&F[p4]);                 // streaming: read-once data
            uchar4 lc = ((const uchar4*)slab)[p4];
            bins[lc.x * 256 + tid] += f.x;
            bins[lc.y * 256 + tid] += f.y;
            bins[lc.z * 256 + tid] += f.z;
            bins[lc.w * 256 + tid] += f.w;
        }
        __syncthreads();

        // tree reduce across tid for each class
        for (int s = 128; s > 0; s >>= 1) {
            if (tid < s) {
                #pragma unroll
                for (int c = 0; c < C_; c++)
                    bins[c * 256 + tid] += bins[c * 256 + tid + s];
            }
            __syncthreads();
        }
        if (tid < C_)
            g_sums[((size_t)(b * C_ + tid)) * D_ + d] = bins[tid * 256];
        __syncthreads();
    }
}

// ---------------- K3: L2-normalize protos ----------------
// grid 336 blocks (b*21+c), 128 threads; each thread owns one float4 (512/128)
__global__ void k3_normalize() {
    int v = blockIdx.x;
    const float4* s = (const float4*)(g_sums + (size_t)v * D_);
    float4 a = s[threadIdx.x];
    float ss = a.x * a.x + a.y * a.y + a.z * a.z + a.w * a.w;
    #pragma unroll
    for (int o = 16; o > 0; o >>= 1) ss += __shfl_xor_sync(0xffffffffu, ss, o);
    __shared__ float ws[4];
    int warp = threadIdx.x >> 5;
    if ((threadIdx.x & 31) == 0) ws[warp] = ss;
    __syncthreads();
    float tot = ws[0] + ws[1] + ws[2] + ws[3];
    float inv = 1.0f / fmaxf(sqrtf(tot), 1e-12f);
    float4 o4 = make_float4(a.x * inv, a.y * inv, a.z * inv, a.w * inv);
    ((float4*)(g_prot + (size_t)v * D_))[threadIdx.x] = o4;
}

// ---------------- K4: Gram block (c,e) + shifted exp-sums ----------------
// grid 441 blocks (c*21+e), 256 threads; thread = (i = tid/16, j = tid%16)
__global__ __launch_bounds__(256) void k4_gram() {
    int c = blockIdx.x / C_;
    int e = blockIdx.x % C_;
    int i = threadIdx.x >> 4;
    int j = threadIdx.x & 15;

    const float4* A  = (const float4*)(g_prot + (size_t)(i * C_ + c) * D_);
    const float4* Bv = (const float4*)(g_prot + (size_t)(j * C_ + e) * D_);

    float ax = 0.f, ay = 0.f, az = 0.f, aw = 0.f;
    #pragma unroll 8
    for (int k = 0; k < D_ / 4; k++) {
        float4 a = __ldg(&A[k]);
        float4 b = __ldg(&Bv[k]);
        ax = fmaf(a.x, b.x, ax);
        ay = fmaf(a.y, b.y, ay);
        az = fmaf(a.z, b.z, az);
        aw = fmaf(a.w, b.w, aw);
    }
    float dot = (ax + ay) + (az + aw);

    bool valid = (g_cnt[i * C_ + c] > 0) && (g_cnt[j * C_ + e] > 0);
    float s    = dot * 10.0f;                 // S = dot / T, T = 0.1
    float term = valid ? expf(s - 10.0f) : 0.0f;   // shift by max possible (1/T)
    float pos  = (valid && (e == c)) ? s : 0.0f;
    float cntv = (valid && (e == c)) ? 1.0f : 0.0f;

    #pragma unroll
    for (int o = 16; o > 0; o >>= 1) {
        term += __shfl_xor_sync(0xffffffffu, term, o);
        pos  += __shfl_xor_sync(0xffffffffu, pos, o);
        cntv += __shfl_xor_sync(0xffffffffu, cntv, o);
    }
    __shared__ float wt[8], wp[8], wc[8];
    int warp = threadIdx.x >> 5;
    if ((threadIdx.x & 31) == 0) { wt[warp] = term; wp[warp] = pos; wc[warp] = cntv; }
    __syncthreads();
    if (threadIdx.x == 0) {
        float T = 0.f, P = 0.f, Cn = 0.f;
        #pragma unroll
        for (int w = 0; w < 8; w++) { T += wt[w]; P += wp[w]; Cn += wc[w]; }
        g_pAll[blockIdx.x] = T;
        if (e == c) { g_pPos[c] = P; g_pCnt[c] = (int)(Cn + 0.5f); }
    }
}

// ---------------- K5: per-class loss + total ----------------
__global__ void k5_final(float* __restrict__ out) {
    int c = threadIdx.x;
    float loss_c = 0.0f;
    if (c < C_) {
        bool present = false;
        #pragma unroll
        for (int b = 0; b < B_; b++) present = present || (g_cnt[b * C_ + c] > 0);
        if (present) {
            float sAll = 0.0f;
            #pragma unroll
            for (int e = 0; e < C_; e++) sAll += g_pAll[c * C_ + e];
            float sDiag = g_pAll[c * C_ + c];
            float lse = 10.0f + logf(sAll + sDiag);   // logaddexp(lse_diag, lse_all)
            int cnt = g_pCnt[c];
            float pm = g_pPos[c] / (float)(cnt > 1 ? cnt : 1);
            loss_c = lse - pm;
        }
    }
    #pragma unroll
    for (int o = 16; o > 0; o >>= 1) loss_c += __shfl_xor_sync(0xffffffffu, loss_c, o);
    if (threadIdx.x == 0) out[0] = loss_c;
}

// ---------------- launch ----------------
extern "C" void kernel_launch(void* const* d_in, const int* in_sizes, int n_in,
                              void* d_out, int out_size) {
    const float* features = (const float*)d_in[0];   // [16,512,64,64] fp32
    const int*   labels   = (const int*)d_in[1];     // [16,513,513] int32
    float* out = (float*)d_out;

    k1_resize_hist<<<B_, 256>>>(labels);
    k2_pool<<<dim3(B_, D_ / DT_), 256>>>(features);
    k3_normalize<<<B_ * C_, 128>>>();
    k4_gram<<<C_ * C_, 256>>>();
    k5_final<<<1, 32>>>(out);
}

// round 2
// speedup vs baseline: 1.5304x; 1.5304x over previous
#include <cuda_runtime.h>
#include <cstdint>

// ---------------- scratch (no allocations allowed) ----------------
#define B_ 16
#define C_ 21
#define D_ 512
#define HW_ 4096          // 64*64
#define LW_ 513
#define NV_ 336           // B_*C_ proto rows
#define GR_ 352           // padded to 11*32

__device__ unsigned char g_lab[B_ * HW_];          // resized labels as u8
__device__ int           g_cnt[B_ * C_];           // per-image class counts
__device__ float         g_sums[B_ * C_ * D_];     // pooled sums
__device__ float         g_prot[B_ * C_ * D_];     // normalized protos
__device__ float         g_S[GR_ * GR_];           // full Gram (scaled by 1/T later)
__device__ float         g_pAll[C_ * C_];          // sum exp(S-10) per (c,e) block
__device__ float         g_pPos[C_];               // sum of valid diag S values
__device__ int           g_pCnt[C_];               // count of valid diag entries

// ---------------- K1: bilinear resize (half-pixel, exact) + histogram ----------------
__global__ void k1_resize_hist(const int* __restrict__ labels) {
    int b = blockIdx.x;
    __shared__ int hist[C_];
    if (threadIdx.x < C_) hist[threadIdx.x] = 0;
    __syncthreads();

    const int* L = labels + (size_t)b * LW_ * LW_;
    for (int p = threadIdx.x; p < HW_; p += blockDim.x) {
        int y = p >> 6, x = p & 63;
        float sy = (y + 0.5f) * 8.015625f - 0.5f;
        float sx = (x + 0.5f) * 8.015625f - 0.5f;
        int y0 = (int)sy; float wy = sy - (float)y0;
        int x0 = (int)sx; float wx = sx - (float)x0;
        const int* r0 = L + y0 * LW_ + x0;
        const int* r1 = r0 + LW_;
        float v00 = (float)r0[0], v01 = (float)r0[1];
        float v10 = (float)r1[0], v11 = (float)r1[1];
        float v = (1.0f - wy) * ((1.0f - wx) * v00 + wx * v01)
                +          wy * ((1.0f - wx) * v10 + wx * v11);
        int c = (int)v;   // exact in fp32
        g_lab[b * HW_ + p] = (unsigned char)c;
        atomicAdd(&hist[c], 1);
    }
    __syncthreads();
    if (threadIdx.x < C_) g_cnt[b * C_ + threadIdx.x] = hist[threadIdx.x];
}

// ---------------- K2: masked per-class pooling (the 134 MB pass) ----------------
#define DT_ 8
__global__ __launch_bounds__(256) void k2_pool(const float* __restrict__ feat) {
    int b  = blockIdx.x;
    int dt = blockIdx.y;
    int tid = threadIdx.x;

    __shared__ unsigned char slab[HW_];
    __shared__ float bins[C_ * 256];

    ((uint4*)slab)[tid] = ((const uint4*)(g_lab + b * HW_))[tid];
    __syncthreads();

    for (int dd = 0; dd < DT_; dd++) {
        int d = dt * DT_ + dd;
        #pragma unroll
        for (int c = 0; c < C_; c++) bins[c * 256 + tid] = 0.0f;

        const float4* F = (const float4*)(feat + ((size_t)(b * D_ + d)) * HW_);
        #pragma unroll
        for (int k = 0; k < 4; k++) {
            int p4 = k * 256 + tid;
            float4 f = __ldcs(&F[p4]);
            uchar4 lc = ((const uchar4*)slab)[p4];
            bins[lc.x * 256 + tid] += f.x;
            bins[lc.y * 256 + tid] += f.y;
            bins[lc.z * 256 + tid] += f.z;
            bins[lc.w * 256 + tid] += f.w;
        }
        __syncthreads();

        for (int s = 128; s > 0; s >>= 1) {
            if (tid < s) {
                #pragma unroll
                for (int c = 0; c < C_; c++)
                    bins[c * 256 + tid] += bins[c * 256 + tid + s];
            }
            __syncthreads();
        }
        if (tid < C_)
            g_sums[((size_t)(b * C_ + tid)) * D_ + d] = bins[tid * 256];
        __syncthreads();
    }
}

// ---------------- K3: L2-normalize protos ----------------
__global__ void k3_normalize() {
    int v = blockIdx.x;
    const float4* s = (const float4*)(g_sums + (size_t)v * D_);
    float4 a = s[threadIdx.x];
    float ss = a.x * a.x + a.y * a.y + a.z * a.z + a.w * a.w;
    #pragma unroll
    for (int o = 16; o > 0; o >>= 1) ss += __shfl_xor_sync(0xffffffffu, ss, o);
    __shared__ float ws[4];
    int warp = threadIdx.x >> 5;
    if ((threadIdx.x & 31) == 0) ws[warp] = ss;
    __syncthreads();
    float tot = ws[0] + ws[1] + ws[2] + ws[3];
    float inv = 1.0f / fmaxf(sqrtf(tot), 1e-12f);
    float4 o4 = make_float4(a.x * inv, a.y * inv, a.z * inv, a.w * inv);
    ((float4*)(g_prot + (size_t)v * D_))[threadIdx.x] = o4;
}

// ---------------- K4a: Gram SGEMM  G = P * P^T  (336x336, K=512) ----------------
// grid (11,11), 128 threads. 32x32 output tile, per-thread 4 rows x 2 cols.
// K staged through smem in 4 chunks of 128 floats (32 f4).
__global__ __launch_bounds__(128) void k4a_gemm() {
    __shared__ float4 As4[32][32];   // [row][k4]
    __shared__ float4 Bs4[32][32];   // [k4][col]

    int t = threadIdx.x;
    int tr = t >> 4;          // 0..7  -> rows tr*4 .. tr*4+3
    int tc = t & 15;          // 0..15 -> cols tc, tc+16
    int rowBase = blockIdx.y * 32;
    int colBase = blockIdx.x * 32;

    float acc[4][2];
    #pragma unroll
    for (int r = 0; r < 4; r++) { acc[r][0] = 0.f; acc[r][1] = 0.f; }

    const float4* P4 = (const float4*)g_prot;   // row stride 128 f4

    for (int kc = 0; kc < 4; kc++) {
        // load A chunk: 32 rows x 32 f4 = 1024 f4, 8 per thread
        #pragma unroll
        for (int m = 0; m < 8; m++) {
            int idx = m * 128 + t;
            int row = idx >> 5, q = idx & 31;
            int v = rowBase + row;
            As4[row][q] = (v < NV_) ? P4[(size_t)v * 128 + kc * 32 + q]
                                    : make_float4(0.f, 0.f, 0.f, 0.f);
        }
        // load B chunk transposed: Bs4[q][col]
        #pragma unroll
        for (int m = 0; m < 8; m++) {
            int idx = m * 128 + t;
            int row = idx >> 5, q = idx & 31;
            int v = colBase + row;
            Bs4[q][row] = (v < NV_) ? P4[(size_t)v * 128 + kc * 32 + q]
                                    : make_float4(0.f, 0.f, 0.f, 0.f);
        }
        __syncthreads();

        #pragma unroll 8
        for (int k4 = 0; k4 < 32; k4++) {
            float4 b0 = Bs4[k4][tc];
            float4 b1 = Bs4[k4][tc + 16];
            #pragma unroll
            for (int r = 0; r < 4; r++) {
                float4 a = As4[tr * 4 + r][k4];
                acc[r][0] = fmaf(a.x, b0.x, fmaf(a.y, b0.y, fmaf(a.z, b0.z, fmaf(a.w, b0.w, acc[r][0]))));
                acc[r][1] = fmaf(a.x, b1.x, fmaf(a.y, b1.y, fmaf(a.z, b1.z, fmaf(a.w, b1.w, acc[r][1]))));
            }
        }
        __syncthreads();
    }

    #pragma unroll
    for (int r = 0; r < 4; r++) {
        int v = rowBase + tr * 4 + r;
        g_S[(size_t)v * GR_ + colBase + tc]      = acc[r][0];
        g_S[(size_t)v * GR_ + colBase + tc + 16] = acc[r][1];
    }
}

// ---------------- K4b: per-(c,e) block exp-sum reduction over Gram ----------------
__global__ __launch_bounds__(256) void k4b_reduce() {
    int c = blockIdx.x / C_;
    int e = blockIdx.x % C_;
    int i = threadIdx.x >> 4;
    int j = threadIdx.x & 15;

    float dot = g_S[(size_t)(i * C_ + c) * GR_ + (j * C_ + e)];
    bool valid = (g_cnt[i * C_ + c] > 0) && (g_cnt[j * C_ + e] > 0);
    float s    = dot * 10.0f;                       // / T
    float term = valid ? expf(s - 10.0f) : 0.0f;    // shift by 1/T (max possible)
    float pos  = (valid && (e == c)) ? s : 0.0f;
    float cntv = (valid && (e == c)) ? 1.0f : 0.0f;

    #pragma unroll
    for (int o = 16; o > 0; o >>= 1) {
        term += __shfl_xor_sync(0xffffffffu, term, o);
        pos  += __shfl_xor_sync(0xffffffffu, pos, o);
        cntv += __shfl_xor_sync(0xffffffffu, cntv, o);
    }
    __shared__ float wt[8], wp[8], wc[8];
    int warp = threadIdx.x >> 5;
    if ((threadIdx.x & 31) == 0) { wt[warp] = term; wp[warp] = pos; wc[warp] = cntv; }
    __syncthreads();
    if (threadIdx.x == 0) {
        float T = 0.f, P = 0.f, Cn = 0.f;
        #pragma unroll
        for (int w = 0; w < 8; w++) { T += wt[w]; P += wp[w]; Cn += wc[w]; }
        g_pAll[blockIdx.x] = T;
        if (e == c) { g_pPos[c] = P; g_pCnt[c] = (int)(Cn + 0.5f); }
    }
}

// ---------------- K5: per-class loss + total ----------------
__global__ void k5_final(float* __restrict__ out) {
    int c = threadIdx.x;
    float loss_c = 0.0f;
    if (c < C_) {
        bool present = false;
        #pragma unroll
        for (int b = 0; b < B_; b++) present = present || (g_cnt[b * C_ + c] > 0);
        if (present) {
            float sAll = 0.0f;
            #pragma unroll
            for (int e = 0; e < C_; e++) sAll += g_pAll[c * C_ + e];
            float sDiag = g_pAll[c * C_ + c];
            float lse = 10.0f + logf(sAll + sDiag);
            int cnt = g_pCnt[c];
            float pm = g_pPos[c] / (float)(cnt > 1 ? cnt : 1);
            loss_c = lse - pm;
        }
    }
    #pragma unroll
    for (int o = 16; o > 0; o >>= 1) loss_c += __shfl_xor_sync(0xffffffffu, loss_c, o);
    if (threadIdx.x == 0) out[0] = loss_c;
}

// ---------------- launch ----------------
extern "C" void kernel_launch(void* const* d_in, const int* in_sizes, int n_in,
                              void* d_out, int out_size) {
    const float* features = (const float*)d_in[0];   // [16,512,64,64] fp32
    const int*   labels   = (const int*)d_in[1];     // [16,513,513] int32
    float* out = (float*)d_out;

    k1_resize_hist<<<B_, 256>>>(labels);
    k2_pool<<<dim3(B_, D_ / DT_), 256>>>(features);
    k3_normalize<<<B_ * C_, 128>>>();
    k4a_gemm<<<dim3(11, 11), 128>>>();
    k4b_reduce<<<C_ * C_, 256>>>();
    k5_final<<<1, 32>>>(out);
}

// round 6
// speedup vs baseline: 2.2478x; 1.4688x over previous
#include <cuda_runtime.h>
#include <cstdint>

// ---------------- scratch (no allocations allowed) ----------------
#define B_ 16
#define C_ 21
#define D_ 512
#define HW_ 4096          // 64*64
#define LW_ 513
#define NV_ 336           // B_*C_ proto rows
#define GR_ 352           // padded to 11*32
#define KZ_ 4             // K-split factor (512/128)

__device__ unsigned char g_lab[B_ * HW_];            // resized labels as u8
__device__ int           g_pres[B_ * C_];            // class present in image (0/1)
__device__ float         g_sums[B_ * C_ * D_];       // pooled (unnormalized) sums
__device__ float         g_Spart[KZ_ * GR_ * GR_];   // partial Grams per K chunk
__device__ float         g_pAll[C_ * C_];            // sum exp(S-10) per (c,e) block
__device__ float         g_pPos[C_];                 // sum of valid diag S values
__device__ int           g_pCnt[C_];                 // count of valid diag entries

// ---------------- K1: bilinear resize (half-pixel, exact) + presence ----------------
// grid (16, 8), 256 threads: block handles 512 pixels of image b
__global__ void k1_resize(const int* __restrict__ labels) {
    int b = blockIdx.x;
    const int* L = labels + (size_t)b * LW_ * LW_;
    int base = blockIdx.y * 512;
    #pragma unroll
    for (int q = 0; q < 2; q++) {
        int p = base + q * 256 + threadIdx.x;
        int y = p >> 6, x = p & 63;
        // src = (i+0.5)*513/64 - 0.5 ; exact in fp32 (multiples of 1/128)
        float sy = (y + 0.5f) * 8.015625f - 0.5f;
        float sx = (x + 0.5f) * 8.015625f - 0.5f;
        int y0 = (int)sy; float wy = sy - (float)y0;
        int x0 = (int)sx; float wx = sx - (float)x0;
        const int* r0 = L + y0 * LW_ + x0;
        const int* r1 = r0 + LW_;
        float v00 = (float)r0[0], v01 = (float)r0[1];
        float v10 = (float)r1[0], v11 = (float)r1[1];
        float v = (1.0f - wy) * ((1.0f - wx) * v00 + wx * v01)
                +          wy * ((1.0f - wx) * v10 + wx * v11);
        int c = (int)v;   // truncation; v exact
        g_lab[b * HW_ + p] = (unsigned char)c;
        g_pres[b * C_ + c] = 1;      // benign race
    }
}

// ---------------- K2: masked per-class pooling (the 134 MB pass) ----------------
// grid (16, 64) ; block = image b, channels [dt*8, dt*8+8)
#define DT_ 8
__global__ __launch_bounds__(256) void k2_pool(const float* __restrict__ feat) {
    int b  = blockIdx.x;
    int dt = blockIdx.y;
    int tid = threadIdx.x;
    int w = tid >> 5, lane = tid & 31;

    __shared__ unsigned char slab[HW_];
    __shared__ float bins[C_ * 256];   // bins[c*256 + tid] : per-thread private column

    ((uint4*)slab)[tid] = ((const uint4*)(g_lab + b * HW_))[tid];
    __syncthreads();

    for (int dd = 0; dd < DT_; dd++) {
        int d = dt * DT_ + dd;
        #pragma unroll
        for (int c = 0; c < C_; c++) bins[c * 256 + tid] = 0.0f;
        // (own column only -> no barrier needed before accumulation)

        const float4* F = (const float4*)(feat + ((size_t)(b * D_ + d)) * HW_);
        #pragma unroll
        for (int k = 0; k < 4; k++) {
            int p4 = k * 256 + tid;
            float4 f = __ldcs(&F[p4]);
            uchar4 lc = ((const uchar4*)slab)[p4];
            bins[lc.x * 256 + tid] += f.x;
            bins[lc.y * 256 + tid] += f.y;
            bins[lc.z * 256 + tid] += f.z;
            bins[lc.w * 256 + tid] += f.w;
        }
        __syncthreads();

        // warp w reduces classes 3w..3w+2 (warps 0..6 cover 21; warp 7 idle)
        #pragma unroll
        for (int q = 0; q < 3; q++) {
            int c = w * 3 + q;
            if (c < C_) {
                float s = 0.0f;
                #pragma unroll
                for (int m = 0; m < 8; m++) s += bins[c * 256 + lane + m * 32];
                #pragma unroll
                for (int o = 16; o > 0; o >>= 1) s += __shfl_xor_sync(0xffffffffu, s, o);
                if (lane == 0)
                    g_sums[((size_t)(b * C_ + c)) * D_ + d] = s;
            }
        }
        __syncthreads();   // reduce done before next channel's clear
    }
}

// ---------------- K4a: partial Gram SGEMM  U_z = S_z * S_z^T ----------------
// grid (11,11,4), 128 threads. 32x32 tile, per-thread 4 rows x 2 cols, K chunk = 128.
__global__ __launch_bounds__(128) void k4a_gemm() {
    __shared__ float4 As4[32][32];   // [row][k4]
    __shared__ float4 Bs4[32][32];   // [k4][col]

    int t = threadIdx.x;
    int tr = t >> 4;          // 0..7  -> rows tr*4 .. tr*4+3
    int tc = t & 15;          // 0..15 -> cols tc, tc+16
    int rowBase = blockIdx.y * 32;
    int colBase = blockIdx.x * 32;
    int kc = blockIdx.z;      // K chunk (32 f4)

    float acc[4][2];
    #pragma unroll
    for (int r = 0; r < 4; r++) { acc[r][0] = 0.f; acc[r][1] = 0.f; }

    const float4* P4 = (const float4*)g_sums;   // row stride 128 f4

    #pragma unroll
    for (int m = 0; m < 8; m++) {
        int idx = m * 128 + t;
        int row = idx >> 5, q = idx & 31;
        int v = rowBase + row;
        As4[row][q] = (v < NV_) ? P4[(size_t)v * 128 + kc * 32 + q]
                                : make_float4(0.f, 0.f, 0.f, 0.f);
    }
    #pragma unroll
    for (int m = 0; m < 8; m++) {
        int idx = m * 128 + t;
        int row = idx >> 5, q = idx & 31;
        int v = colBase + row;
        Bs4[q][row] = (v < NV_) ? P4[(size_t)v * 128 + kc * 32 + q]
                                : make_float4(0.f, 0.f, 0.f, 0.f);
    }
    __syncthreads();

    #pragma unroll 8
    for (int k4 = 0; k4 < 32; k4++) {
        float4 b0 = Bs4[k4][tc];
        float4 b1 = Bs4[k4][tc + 16];
        #pragma unroll
        for (int r = 0; r < 4; r++) {
            float4 a = As4[tr * 4 + r][k4];
            acc[r][0] = fmaf(a.x, b0.x, fmaf(a.y, b0.y, fmaf(a.z, b0.z, fmaf(a.w, b0.w, acc[r][0]))));
            acc[r][1] = fmaf(a.x, b1.x, fmaf(a.y, b1.y, fmaf(a.z, b1.z, fmaf(a.w, b1.w, acc[r][1]))));
        }
    }

    float* out = g_Spart + (size_t)kc * GR_ * GR_;
    #pragma unroll
    for (int r = 0; r < 4; r++) {
        int v = rowBase + tr * 4 + r;
        out[(size_t)v * GR_ + colBase + tc]      = acc[r][0];
        out[(size_t)v * GR_ + colBase + tc + 16] = acc[r][1];
    }
}

// ---------------- K4b: per-(c,e) block: normalize via diag, exp-sum reduce ----------------
__global__ __launch_bounds__(256) void k4b_reduce() {
    int c = blockIdx.x / C_;
    int e = blockIdx.x % C_;
    int tid = threadIdx.x;
    int i = tid >> 4;
    int j = tid & 15;

    __shared__ float rnA[16], rnB[16];   // 1/max(norm,eps) for row protos / col protos
    if (tid < 16) {
        int v = tid * C_ + c;
        float dsum = 0.f;
        #pragma unroll
        for (int z = 0; z < KZ_; z++) dsum += g_Spart[(size_t)z * GR_ * GR_ + (size_t)v * GR_ + v];
        rnA[tid] = 1.0f / fmaxf(sqrtf(dsum), 1e-12f);
    } else if (tid < 32) {
        int jj = tid - 16;
        int v = jj * C_ + e;
        float dsum = 0.f;
        #pragma unroll
        for (int z = 0; z < KZ_; z++) dsum += g_Spart[(size_t)z * GR_ * GR_ + (size_t)v * GR_ + v];
        rnB[jj] = 1.0f / fmaxf(sqrtf(dsum), 1e-12f);
    }
    __syncthreads();

    int vi = i * C_ + c, vj = j * C_ + e;
    float u = 0.f;
    #pragma unroll
    for (int z = 0; z < KZ_; z++) u += g_Spart[(size_t)z * GR_ * GR_ + (size_t)vi * GR_ + vj];
    float dot = u * rnA[i] * rnB[j];

    bool valid = (g_pres[vi] != 0) && (g_pres[vj] != 0);
    float s    = dot * 10.0f;                       // / T
    float term = valid ? expf(s - 10.0f) : 0.0f;    // shift by 1/T (max possible)
    float pos  = (valid && (e == c)) ? s : 0.0f;
    float cntv = (valid && (e == c)) ? 1.0f : 0.0f;

    #pragma unroll
    for (int o = 16; o > 0; o >>= 1) {
        term += __shfl_xor_sync(0xffffffffu, term, o);
        pos  += __shfl_xor_sync(0xffffffffu, pos, o);
        cntv += __shfl_xor_sync(0xffffffffu, cntv, o);
    }
    __shared__ float wt[8], wp[8], wc[8];
    int warp = tid >> 5;
    if ((tid & 31) == 0) { wt[warp] = term; wp[warp] = pos; wc[warp] = cntv; }
    __syncthreads();
    if (tid == 0) {
        float T = 0.f, P = 0.f, Cn = 0.f;
        #pragma unroll
        for (int w = 0; w < 8; w++) { T += wt[w]; P += wp[w]; Cn += wc[w]; }
        g_pAll[blockIdx.x] = T;
        if (e == c) { g_pPos[c] = P; g_pCnt[c] = (int)(Cn + 0.5f); }
    }
}

// ---------------- K5: per-class loss + total ----------------
__global__ void k5_final(float* __restrict__ out) {
    int c = threadIdx.x;
    float loss_c = 0.0f;
    if (c < C_) {
        bool present = false;
        #pragma unroll
        for (int b = 0; b < B_; b++) present = present || (g_pres[b * C_ + c] != 0);
        if (present) {
            float sAll = 0.0f;
            #pragma unroll
            for (int e = 0; e < C_; e++) sAll += g_pAll[c * C_ + e];
            float sDiag = g_pAll[c * C_ + c];
            float lse = 10.0f + logf(sAll + sDiag);
            int cnt = g_pCnt[c];
            float pm = g_pPos[c] / (float)(cnt > 1 ? cnt : 1);
            loss_c = lse - pm;
        }
    }
    #pragma unroll
    for (int o = 16; o > 0; o >>= 1) loss_c += __shfl_xor_sync(0xffffffffu, loss_c, o);
    if (threadIdx.x == 0) out[0] = loss_c;
}

// ---------------- launch ----------------
extern "C" void kernel_launch(void* const* d_in, const int* in_sizes, int n_in,
                              void* d_out, int out_size) {
    const float* features = (const float*)d_in[0];   // [16,512,64,64] fp32
    const int*   labels   = (const int*)d_in[1];     // [16,513,513] int32
    float* out = (float*)d_out;

    void* presPtr = nullptr;
    cudaGetSymbolAddress(&presPtr, g_pres);
    cudaMemsetAsync(presPtr, 0, B_ * C_ * sizeof(int));

    k1_resize<<<dim3(B_, 8), 256>>>(labels);
    k2_pool<<<dim3(B_, D_ / DT_), 256>>>(features);
    k4a_gemm<<<dim3(11, 11, KZ_), 128>>>();
    k4b_reduce<<<C_ * C_, 256>>>();
    k5_final<<<1, 32>>>(out);
}